// round 10
// baseline (speedup 1.0000x reference)
#include <cuda_runtime.h>
#include <math.h>

#define TSEQ 500
#define BATCH 512

typedef unsigned long long u64;

__device__ __forceinline__ void ffma2(u64& d, u64 a, u64 b, u64 c) {
    asm("fma.rn.f32x2 %0, %1, %2, %3;" : "=l"(d) : "l"(a), "l"(b), "l"(c));
}
__device__ __forceinline__ float2 up2(u64 v) {
    float2 f; asm("mov.b64 {%0,%1}, %2;" : "=f"(f.x), "=f"(f.y) : "l"(v)); return f;
}
__device__ __forceinline__ u64 pk2(float x, float y) {
    u64 v; asm("mov.b64 %0, {%1,%2};" : "=l"(v) : "f"(x), "f"(y)); return v;
}

// 128 threads: rg = tid>>3 (16 row-groups x 4 rows), cg = tid&7 (8 col-groups x 8 cols).
// Thread (rg,cg) owns P[4rg..4rg+3][8cg..8cg+7] as 16 packed f32x2 registers.
// mu[c0..c0+7] replicated in EVERY thread's registers (identical updates).
// K=4 blocked sequential measurement updates, ONE barrier per block:
//  - V = P H^T via 4-shuffle octet reduce-scatter per row
//  - 10 Gram entries + 4 innovations via one 16-value/16-lane butterfly
//    reduce-scatter; z contributed only by lanes 0-7 (rg%4==0) of each warp,
//    so the 4-warp merge holds exactly 4*z -> exact *0.25f recovery.

__global__ void __launch_bounds__(128, 4)
akf_main(const float* __restrict__ ext, const float* __restrict__ obs,
         const float* __restrict__ mu0, const float* __restrict__ sg0,
         const float* __restrict__ lsig, const float* __restrict__ Bm,
         const float* __restrict__ Hm, const float* __restrict__ ldel,
         float* __restrict__ out)
{
    __shared__ __align__(16) float sh_H[4096];
    __shared__ __align__(16) float sh_B[2048];
    __shared__ __align__(16) float sh_V[2][4][64];
    __shared__ __align__(16) float sh_GP[2][14][4];  // [pb][entry][warp]
    __shared__ __align__(16) float sh_mu[64];
    __shared__ float sh_y[64], sh_u[32], sh_r[64], sh_q[64];

    const int b    = blockIdx.x;
    const int tid  = threadIdx.x;
    const int rg   = tid >> 3;
    const int cg   = tid & 7;
    const int r0   = rg << 2;
    const int c0   = cg << 3;
    const int lane = tid & 31;
    const int wid  = tid >> 5;
    const int s1 = cg & 1, s2 = (cg >> 1) & 1;
    const bool zon = (lane < 8);   // rg % 4 == 0 within the warp

    for (int i = tid; i < 4096; i += 128) sh_H[i] = Hm[i];
    for (int i = tid; i < 2048; i += 128) sh_B[i] = Bm[i];
    if (tid < 64) {
        float e = expf(ldel[tid]); sh_r[tid] = e * e;
        float f = expf(lsig[tid]); sh_q[tid] = f * f;
    }

    u64 P2[4][4];
    #pragma unroll
    for (int a = 0; a < 4; ++a)
        #pragma unroll
        for (int k = 0; k < 4; ++k) P2[a][k] = 0ull;

    float* outmu = out;
    float* outls = out + (size_t)TSEQ * BATCH * 64;

    if (tid < 64) {
        float m0  = mu0[b * 64 + tid];
        float s0v = sg0[b * 64 + tid];
        sh_mu[tid] = m0;
        outmu[b * 64 + tid] = m0;
        outls[b * 64 + tid] = logf(s0v);
    }
    #pragma unroll
    for (int a = 0; a < 4; ++a) {
        int d = r0 + a;
        if ((d >> 3) == cg) {
            float s0v = sg0[b * 64 + d];
            int kk = (d & 7) >> 1;
            float2 e = up2(P2[a][kk]);
            if (d & 1) e.y = s0v * s0v; else e.x = s0v * s0v;
            P2[a][kk] = pk2(e.x, e.y);
        }
    }
    __syncthreads();

    for (int t = 1; t < TSEQ; ++t) {
        if (tid < 64) sh_y[tid] = obs[((size_t)t * BATCH + b) * 64 + tid];
        if (tid < 32) sh_u[tid] = ext[((size_t)(t - 1) * BATCH + b) * 32 + tid];
        __syncthreads();

        // ---- predict: mu += B u (smem) ; P += diag(q) ----
        if (tid < 64) {
            float s = sh_mu[tid];
            const float* Br = &sh_B[tid * 32];
            #pragma unroll 8
            for (int k = 0; k < 32; ++k) s += Br[k] * sh_u[k];
            sh_mu[tid] = s;
        }
        #pragma unroll
        for (int a = 0; a < 4; ++a) {
            int d = r0 + a;
            if ((d >> 3) == cg) {
                int kk = (d & 7) >> 1;
                float2 e = up2(P2[a][kk]);
                if (d & 1) e.y += sh_q[d]; else e.x += sh_q[d];
                P2[a][kk] = pk2(e.x, e.y);
            }
        }
        __syncthreads();

        // mu col strip -> EVERY thread's registers (replicated)
        u64 mc2[4];
        {
            const ulonglong2* mp = (const ulonglong2*)&sh_mu[c0];
            ulonglong2 ma = mp[0], mb = mp[1];
            mc2[0] = ma.x; mc2[1] = ma.y; mc2[2] = mb.x; mc2[3] = mb.y;
        }

        // ---- 16 blocks of 4 observations, one barrier each ----
        #pragma unroll 1
        for (int blk = 0; blk < 16; ++blk) {
            const int o  = blk << 2;
            const int pb = blk & 1;
            float* V = &sh_V[pb][0][0];

            // ---- phase 1a: vp[j][a] partials, V rows, z partials ----
            float vp[4][4];
            float zz[4];
            #pragma unroll
            for (int j = 0; j < 4; ++j) {
                const ulonglong2* hp = (const ulonglong2*)&sh_H[((o + j) << 6) + c0];
                ulonglong2 ha = hp[0], hb = hp[1];
                u64 h2[4] = {ha.x, ha.y, hb.x, hb.y};
                #pragma unroll
                for (int a = 0; a < 4; ++a) {
                    u64 acc = 0ull;
                    ffma2(acc, P2[a][0], h2[0], acc);
                    ffma2(acc, P2[a][1], h2[1], acc);
                    ffma2(acc, P2[a][2], h2[2], acc);
                    ffma2(acc, P2[a][3], h2[3], acc);
                    float2 f = up2(acc);
                    vp[j][a] = f.x + f.y;
                }
                // octet reduce-scatter (4 shuffles) -> V row j
                float ka = s1 ? vp[j][2] : vp[j][0];
                float kb = s1 ? vp[j][3] : vp[j][1];
                float sa = s1 ? vp[j][0] : vp[j][2];
                float sb = s1 ? vp[j][1] : vp[j][3];
                ka += __shfl_xor_sync(0xffffffffu, sa, 1);
                kb += __shfl_xor_sync(0xffffffffu, sb, 1);
                float kc = s2 ? kb : ka;
                float sc = s2 ? ka : kb;
                kc += __shfl_xor_sync(0xffffffffu, sc, 2);
                kc += __shfl_xor_sync(0xffffffffu, kc, 4);
                if (cg < 4) V[j * 64 + r0 + 2 * s1 + s2] = kc;
                // innovation partial: z_j = h_j . mu (only lanes 0-7 contribute)
                u64 za = 0ull;
                ffma2(za, h2[0], mc2[0], za);
                ffma2(za, h2[1], mc2[1], za);
                ffma2(za, h2[2], mc2[2], za);
                ffma2(za, h2[3], mc2[3], za);
                float2 zf = up2(za);
                zz[j] = zon ? (zf.x + zf.y) : 0.0f;
            }

            // ---- phase 1b: Gram partials + 16-value reduce-scatter ----
            {
                float4 hq0 = *(const float4*)&sh_H[((o + 0) << 6) + r0];
                float4 hq1 = *(const float4*)&sh_H[((o + 1) << 6) + r0];
                float4 hq2 = *(const float4*)&sh_H[((o + 2) << 6) + r0];
                float4 hq3 = *(const float4*)&sh_H[((o + 3) << 6) + r0];
                float val[16];
                val[0]  = hq0.x*vp[0][0] + hq0.y*vp[0][1] + hq0.z*vp[0][2] + hq0.w*vp[0][3]; // G00
                val[1]  = hq1.x*vp[0][0] + hq1.y*vp[0][1] + hq1.z*vp[0][2] + hq1.w*vp[0][3]; // G10
                val[2]  = hq1.x*vp[1][0] + hq1.y*vp[1][1] + hq1.z*vp[1][2] + hq1.w*vp[1][3]; // G11
                val[3]  = hq2.x*vp[0][0] + hq2.y*vp[0][1] + hq2.z*vp[0][2] + hq2.w*vp[0][3]; // G20
                val[4]  = hq2.x*vp[1][0] + hq2.y*vp[1][1] + hq2.z*vp[1][2] + hq2.w*vp[1][3]; // G21
                val[5]  = hq2.x*vp[2][0] + hq2.y*vp[2][1] + hq2.z*vp[2][2] + hq2.w*vp[2][3]; // G22
                val[6]  = hq3.x*vp[0][0] + hq3.y*vp[0][1] + hq3.z*vp[0][2] + hq3.w*vp[0][3]; // G30
                val[7]  = hq3.x*vp[1][0] + hq3.y*vp[1][1] + hq3.z*vp[1][2] + hq3.w*vp[1][3]; // G31
                val[8]  = hq3.x*vp[2][0] + hq3.y*vp[2][1] + hq3.z*vp[2][2] + hq3.w*vp[2][3]; // G32
                val[9]  = hq3.x*vp[3][0] + hq3.y*vp[3][1] + hq3.z*vp[3][2] + hq3.w*vp[3][3]; // G33
                val[10] = zz[0]; val[11] = zz[1]; val[12] = zz[2]; val[13] = zz[3];
                val[14] = 0.0f;  val[15] = 0.0f;

                const bool b3 = lane & 8, b2l = lane & 4, b1 = lane & 2, b0 = lane & 1;
                #pragma unroll
                for (int k = 0; k < 8; ++k) {
                    float keep = b3 ? val[k + 8] : val[k];
                    float send = b3 ? val[k]     : val[k + 8];
                    val[k] = keep + __shfl_xor_sync(0xffffffffu, send, 8);
                }
                #pragma unroll
                for (int k = 0; k < 4; ++k) {
                    float keep = b2l ? val[k + 4] : val[k];
                    float send = b2l ? val[k]     : val[k + 4];
                    val[k] = keep + __shfl_xor_sync(0xffffffffu, send, 4);
                }
                #pragma unroll
                for (int k = 0; k < 2; ++k) {
                    float keep = b1 ? val[k + 2] : val[k];
                    float send = b1 ? val[k]     : val[k + 2];
                    val[k] = keep + __shfl_xor_sync(0xffffffffu, send, 2);
                }
                {
                    float keep = b0 ? val[1] : val[0];
                    float send = b0 ? val[0] : val[1];
                    val[0] = keep + __shfl_xor_sync(0xffffffffu, send, 1);
                }
                val[0] += __shfl_xor_sync(0xffffffffu, val[0], 16);
                if (lane < 14) sh_GP[pb][lane][wid] = val[0];
            }
            __syncthreads();   // the ONLY barrier per block

            // ---- phase 3: merge warp partials, K-space recursion (exact) ----
            #define GSUM(e) ({ float4 qq = *(const float4*)&sh_GP[pb][e][0]; \
                               (qq.x + qq.y) + (qq.z + qq.w); })
            float g00 = GSUM(0), u01 = GSUM(1), g11 = GSUM(2), u02 = GSUM(3);
            float g21 = GSUM(4), g22 = GSUM(5), u03 = GSUM(6), g31 = GSUM(7);
            float g32 = GSUM(8), g33 = GSUM(9);
            // z entries: each warp contributed the exact z_j -> merged = 4*z_j
            float z0 = GSUM(10) * 0.25f, z1 = GSUM(11) * 0.25f;
            float z2 = GSUM(12) * 0.25f, z3 = GSUM(13) * 0.25f;
            #undef GSUM

            float rs0 = __fdividef(1.0f, g00 + sh_r[o + 0]);
            float c01 = u01 * rs0, c02 = u02 * rs0, c03 = u03 * rs0;
            float u12 = g21 - c01 * u02;
            float u13 = g31 - c01 * u03;
            float rs1 = __fdividef(1.0f, (g11 - c01 * u01) + sh_r[o + 1]);
            float c12 = u12 * rs1, c13 = u13 * rs1;
            float u23 = g32 - c02 * u03 - c12 * u13;
            float rs2 = __fdividef(1.0f, (g22 - c02 * u02 - c12 * u12) + sh_r[o + 2]);
            float c23 = u23 * rs2;
            float rs3 = __fdividef(1.0f, (g33 - c03 * u03 - c13 * u13 - c23 * u23) + sh_r[o + 3]);
            float f0 = (sh_y[o + 0] - z0) * rs0;
            float f1 = (sh_y[o + 1] - z1 - u01 * f0) * rs1;
            float f2 = (sh_y[o + 2] - z2 - u02 * f0 - u12 * f1) * rs2;
            float f3 = (sh_y[o + 3] - z3 - u03 * f0 - u13 * f1 - u23 * f2) * rs3;

            // ---- phase 4: w strips, rank-4 update, mu update (all threads) ----
            u64 wc[4][4];
            {
                const ulonglong2* q0 = (const ulonglong2*)&V[0 * 64 + c0];
                const ulonglong2* q1 = (const ulonglong2*)&V[1 * 64 + c0];
                const ulonglong2* q2 = (const ulonglong2*)&V[2 * 64 + c0];
                const ulonglong2* q3 = (const ulonglong2*)&V[3 * 64 + c0];
                ulonglong2 a0 = q0[0], e0 = q0[1];
                wc[0][0] = a0.x; wc[0][1] = a0.y; wc[0][2] = e0.x; wc[0][3] = e0.y;
                ulonglong2 a1 = q1[0], e1 = q1[1];
                wc[1][0] = a1.x; wc[1][1] = a1.y; wc[1][2] = e1.x; wc[1][3] = e1.y;
                ulonglong2 a2 = q2[0], e2 = q2[1];
                wc[2][0] = a2.x; wc[2][1] = a2.y; wc[2][2] = e2.x; wc[2][3] = e2.y;
                ulonglong2 a3 = q3[0], e3 = q3[1];
                wc[3][0] = a3.x; wc[3][1] = a3.y; wc[3][2] = e3.x; wc[3][3] = e3.y;
                u64 n01 = pk2(-c01, -c01), n02 = pk2(-c02, -c02), n03 = pk2(-c03, -c03);
                u64 n12 = pk2(-c12, -c12), n13 = pk2(-c13, -c13), n23 = pk2(-c23, -c23);
                #pragma unroll
                for (int k = 0; k < 4; ++k) {
                    ffma2(wc[1][k], n01, wc[0][k], wc[1][k]);
                    ffma2(wc[2][k], n02, wc[0][k], wc[2][k]);
                    ffma2(wc[2][k], n12, wc[1][k], wc[2][k]);
                    ffma2(wc[3][k], n03, wc[0][k], wc[3][k]);
                    ffma2(wc[3][k], n13, wc[1][k], wc[3][k]);
                    ffma2(wc[3][k], n23, wc[2][k], wc[3][k]);
                }
            }
            float4 w0r = *(const float4*)&V[0 * 64 + r0];
            float4 w1r = *(const float4*)&V[1 * 64 + r0];
            float4 w2r = *(const float4*)&V[2 * 64 + r0];
            float4 w3r = *(const float4*)&V[3 * 64 + r0];
            w1r.x -= c01 * w0r.x; w1r.y -= c01 * w0r.y; w1r.z -= c01 * w0r.z; w1r.w -= c01 * w0r.w;
            w2r.x -= c02 * w0r.x + c12 * w1r.x; w2r.y -= c02 * w0r.y + c12 * w1r.y;
            w2r.z -= c02 * w0r.z + c12 * w1r.z; w2r.w -= c02 * w0r.w + c12 * w1r.w;
            w3r.x -= c03 * w0r.x + c13 * w1r.x + c23 * w2r.x;
            w3r.y -= c03 * w0r.y + c13 * w1r.y + c23 * w2r.y;
            w3r.z -= c03 * w0r.z + c13 * w1r.z + c23 * w2r.z;
            w3r.w -= c03 * w0r.w + c13 * w1r.w + c23 * w2r.w;

            #pragma unroll
            for (int i = 0; i < 4; ++i) {
                float4 wr = (i == 0) ? w0r : (i == 1) ? w1r : (i == 2) ? w2r : w3r;
                float rsv = (i == 0) ? rs0 : (i == 1) ? rs1 : (i == 2) ? rs2 : rs3;
                float e0 = -wr.x * rsv, e1 = -wr.y * rsv, e2 = -wr.z * rsv, e3 = -wr.w * rsv;
                u64 ga = pk2(e0, e0), gb = pk2(e1, e1), gc = pk2(e2, e2), gd = pk2(e3, e3);
                #pragma unroll
                for (int k = 0; k < 4; ++k) {
                    ffma2(P2[0][k], ga, wc[i][k], P2[0][k]);
                    ffma2(P2[1][k], gb, wc[i][k], P2[1][k]);
                    ffma2(P2[2][k], gc, wc[i][k], P2[2][k]);
                    ffma2(P2[3][k], gd, wc[i][k], P2[3][k]);
                }
            }
            {
                u64 f02 = pk2(f0, f0), f12 = pk2(f1, f1);
                u64 f22 = pk2(f2, f2), f32 = pk2(f3, f3);
                #pragma unroll
                for (int k = 0; k < 4; ++k) {
                    ffma2(mc2[k], f02, wc[0][k], mc2[k]);
                    ffma2(mc2[k], f12, wc[1][k], mc2[k]);
                    ffma2(mc2[k], f22, wc[2][k], mc2[k]);
                    ffma2(mc2[k], f32, wc[3][k], mc2[k]);
                }
            }
        }

        // ---- outputs ; publish mu for next predict ----
        if (tid < 8) {
            float2 m0f = up2(mc2[0]), m1f = up2(mc2[1]);
            float2 m2f = up2(mc2[2]), m3f = up2(mc2[3]);
            float4 lo = make_float4(m0f.x, m0f.y, m1f.x, m1f.y);
            float4 hi = make_float4(m2f.x, m2f.y, m3f.x, m3f.y);
            float* op = &outmu[((size_t)t * BATCH + b) * 64 + c0];
            *(float4*)op = lo;
            *(float4*)(op + 4) = hi;
            *(float4*)&sh_mu[c0] = lo;
            *(float4*)&sh_mu[c0 + 4] = hi;
        }
        #pragma unroll
        for (int a = 0; a < 4; ++a) {
            int d = r0 + a;
            if ((d >> 3) == cg) {
                float2 e = up2(P2[a][(d & 7) >> 1]);
                float dv = (d & 1) ? e.y : e.x;
                outls[((size_t)t * BATCH + b) * 64 + d] = 0.5f * logf(dv);
            }
        }
        __syncthreads();
    }
}

extern "C" void kernel_launch(void* const* d_in, const int* in_sizes, int n_in,
                              void* d_out, int out_size) {
    const float* ext  = (const float*)d_in[0];   // (500, 512, 32)
    const float* obs  = (const float*)d_in[1];   // (500, 512, 64)
    const float* mu0  = (const float*)d_in[2];   // (512, 64)
    const float* sg0  = (const float*)d_in[3];   // (512, 64)
    const float* lsig = (const float*)d_in[4];   // (64,)
    const float* Bm   = (const float*)d_in[5];   // (64, 32)
    const float* H    = (const float*)d_in[6];   // (64, 64)
    const float* ldel = (const float*)d_in[7];   // (64,)
    float* out = (float*)d_out;

    akf_main<<<BATCH, 128>>>(ext, obs, mu0, sg0, lsig, Bm, H, ldel, out);
}

// round 11
// speedup vs baseline: 1.1697x; 1.1697x over previous
#include <cuda_runtime.h>
#include <math.h>

#define TSEQ 500
#define BATCH 512

typedef unsigned long long u64;

__device__ __forceinline__ void ffma2(u64& d, u64 a, u64 b, u64 c) {
    asm("fma.rn.f32x2 %0, %1, %2, %3;" : "=l"(d) : "l"(a), "l"(b), "l"(c));
}
__device__ __forceinline__ float2 up2(u64 v) {
    float2 f; asm("mov.b64 {%0,%1}, %2;" : "=f"(f.x), "=f"(f.y) : "l"(v)); return f;
}
__device__ __forceinline__ u64 pk2(float x, float y) {
    u64 v; asm("mov.b64 %0, {%1,%2};" : "=l"(v) : "f"(x), "f"(y)); return v;
}

// CTA = 128 threads = 2 independent batch-halves of 64 threads (2 warps each).
// Within a half: ht = tid&63, rg = ht>>3 (8 row-groups x 8 rows), cg = ht&7 (8 cols).
// Thread owns P[8rg..8rg+7][8cg..8cg+7] as P2[8][4] packed f32x2 (64 regs).
// K=4 blocked sequential measurement updates, ONE barrier per block.
// mu col strip replicated in every thread's registers.

__global__ void __launch_bounds__(128, 2)
akf_main(const float* __restrict__ ext, const float* __restrict__ obs,
         const float* __restrict__ mu0, const float* __restrict__ sg0,
         const float* __restrict__ lsig, const float* __restrict__ Bm,
         const float* __restrict__ Hm, const float* __restrict__ ldel,
         float* __restrict__ out)
{
    __shared__ __align__(16) float sh_H[4096];
    __shared__ __align__(16) float sh_B[2048];
    __shared__ __align__(16) float sh_V[2][2][4][64];   // [half][pb][j][row]
    __shared__ __align__(16) float sh_GP[2][2][14][2];  // [half][pb][entry][warp]
    __shared__ __align__(16) float sh_mu[2][64];
    __shared__ __align__(16) float sh_y[2][64];
    __shared__ float sh_u[2][32], sh_r[64], sh_q[64];

    const int tid  = threadIdx.x;
    const int half = tid >> 6;
    const int ht   = tid & 63;
    const int b    = (blockIdx.x << 1) | half;
    const int rg   = ht >> 3;
    const int cg   = ht & 7;
    const int r0   = rg << 3;
    const int c0   = cg << 3;
    const int lane = tid & 31;
    const int wh   = (ht >> 5) & 1;
    const bool zon = (lane < 8);
    const bool diag = (rg == cg);
    const bool bb2 = cg & 4, bb1 = cg & 2, bb0 = cg & 1;

    for (int i = tid; i < 4096; i += 128) sh_H[i] = Hm[i];
    for (int i = tid; i < 2048; i += 128) sh_B[i] = Bm[i];
    if (tid < 64) {
        float e = expf(ldel[tid]); sh_r[tid] = e * e;
        float f = expf(lsig[tid]); sh_q[tid] = f * f;
    }

    u64 P2[8][4];
    #pragma unroll
    for (int a = 0; a < 8; ++a)
        #pragma unroll
        for (int k = 0; k < 4; ++k) P2[a][k] = 0ull;

    float* outmu = out;
    float* outls = out + (size_t)TSEQ * BATCH * 64;

    {
        float m0  = mu0[b * 64 + ht];
        float s0v = sg0[b * 64 + ht];
        sh_mu[half][ht] = m0;
        outmu[b * 64 + ht] = m0;
        outls[b * 64 + ht] = logf(s0v);
    }
    if (diag) {
        #pragma unroll
        for (int a = 0; a < 8; ++a) {
            float s0v = sg0[b * 64 + r0 + a];
            float2 e = up2(P2[a][a >> 1]);
            if (a & 1) e.y = s0v * s0v; else e.x = s0v * s0v;
            P2[a][a >> 1] = pk2(e.x, e.y);
        }
    }
    __syncthreads();

    for (int t = 1; t < TSEQ; ++t) {
        sh_y[half][ht] = obs[((size_t)t * BATCH + b) * 64 + ht];
        if (ht < 32) sh_u[half][ht] = ext[((size_t)(t - 1) * BATCH + b) * 32 + ht];
        __syncthreads();

        // ---- predict: mu += B u ; P += diag(q) ----
        {
            float s = sh_mu[half][ht];
            const float* Br = &sh_B[ht * 32];
            #pragma unroll 8
            for (int k = 0; k < 32; ++k) s += Br[k] * sh_u[half][k];
            sh_mu[half][ht] = s;
        }
        if (diag) {
            #pragma unroll
            for (int a = 0; a < 8; ++a) {
                float qv = sh_q[r0 + a];
                float2 e = up2(P2[a][a >> 1]);
                if (a & 1) e.y += qv; else e.x += qv;
                P2[a][a >> 1] = pk2(e.x, e.y);
            }
        }
        __syncthreads();

        // mu col strip -> every thread's registers (replicated)
        u64 mc2[4];
        {
            const ulonglong2* mp = (const ulonglong2*)&sh_mu[half][c0];
            ulonglong2 ma = mp[0], mb = mp[1];
            mc2[0] = ma.x; mc2[1] = ma.y; mc2[2] = mb.x; mc2[3] = mb.y;
        }

        // ---- 16 blocks of 4 observations, one barrier each ----
        #pragma unroll 1
        for (int blk = 0; blk < 16; ++blk) {
            const int o  = blk << 2;
            const int pb = blk & 1;
            float* V = &sh_V[half][pb][0][0];

            // phase 1a: vp[j][a] partials, V rows, z partials
            float vp[4][8];
            float zz[4];
            #pragma unroll
            for (int j = 0; j < 4; ++j) {
                const ulonglong2* hp = (const ulonglong2*)&sh_H[((o + j) << 6) + c0];
                ulonglong2 ha = hp[0], hb = hp[1];
                u64 h2[4] = {ha.x, ha.y, hb.x, hb.y};
                #pragma unroll
                for (int a = 0; a < 8; ++a) {
                    u64 acc = 0ull;
                    ffma2(acc, P2[a][0], h2[0], acc);
                    ffma2(acc, P2[a][1], h2[1], acc);
                    ffma2(acc, P2[a][2], h2[2], acc);
                    ffma2(acc, P2[a][3], h2[3], acc);
                    float2 f = up2(acc);
                    vp[j][a] = f.x + f.y;
                }
                // reduce-scatter 8 values over the 8-lane octet (7 shuffles)
                float k4[4], k2[2];
                #pragma unroll
                for (int m = 0; m < 4; ++m) {
                    float keep = bb2 ? vp[j][m + 4] : vp[j][m];
                    float send = bb2 ? vp[j][m]     : vp[j][m + 4];
                    k4[m] = keep + __shfl_xor_sync(0xffffffffu, send, 4);
                }
                #pragma unroll
                for (int m = 0; m < 2; ++m) {
                    float keep = bb1 ? k4[m + 2] : k4[m];
                    float send = bb1 ? k4[m]     : k4[m + 2];
                    k2[m] = keep + __shfl_xor_sync(0xffffffffu, send, 2);
                }
                float keep = bb0 ? k2[1] : k2[0];
                float send = bb0 ? k2[0] : k2[1];
                float kk = keep + __shfl_xor_sync(0xffffffffu, send, 1);
                V[(j << 6) + ht] = kk;   // lane holds v[row r0+cg] = v[ht]
                // innovation partial (counted once per warp via zon)
                u64 za = 0ull;
                ffma2(za, h2[0], mc2[0], za);
                ffma2(za, h2[1], mc2[1], za);
                ffma2(za, h2[2], mc2[2], za);
                ffma2(za, h2[3], mc2[3], za);
                float2 zf = up2(za);
                zz[j] = zon ? (zf.x + zf.y) : 0.0f;
            }

            // phase 1b: Gram partials + 16-value/16-lane butterfly reduce-scatter
            {
                float4 hqa[4], hqb[4];
                #pragma unroll
                for (int j = 0; j < 4; ++j) {
                    hqa[j] = *(const float4*)&sh_H[((o + j) << 6) + r0];
                    hqb[j] = *(const float4*)&sh_H[((o + j) << 6) + r0 + 4];
                }
                #define DOT8(j, k) (hqa[j].x*vp[k][0] + hqa[j].y*vp[k][1] + hqa[j].z*vp[k][2] + hqa[j].w*vp[k][3] \
                                  + hqb[j].x*vp[k][4] + hqb[j].y*vp[k][5] + hqb[j].z*vp[k][6] + hqb[j].w*vp[k][7])
                float val[16];
                val[0] = DOT8(0, 0); val[1] = DOT8(1, 0); val[2] = DOT8(1, 1);
                val[3] = DOT8(2, 0); val[4] = DOT8(2, 1); val[5] = DOT8(2, 2);
                val[6] = DOT8(3, 0); val[7] = DOT8(3, 1); val[8] = DOT8(3, 2);
                val[9] = DOT8(3, 3);
                #undef DOT8
                val[10] = zz[0]; val[11] = zz[1]; val[12] = zz[2]; val[13] = zz[3];
                val[14] = 0.0f;  val[15] = 0.0f;

                const bool b3 = lane & 8, b2l = lane & 4, b1 = lane & 2, b0 = lane & 1;
                #pragma unroll
                for (int k = 0; k < 8; ++k) {
                    float keep = b3 ? val[k + 8] : val[k];
                    float send = b3 ? val[k]     : val[k + 8];
                    val[k] = keep + __shfl_xor_sync(0xffffffffu, send, 8);
                }
                #pragma unroll
                for (int k = 0; k < 4; ++k) {
                    float keep = b2l ? val[k + 4] : val[k];
                    float send = b2l ? val[k]     : val[k + 4];
                    val[k] = keep + __shfl_xor_sync(0xffffffffu, send, 4);
                }
                #pragma unroll
                for (int k = 0; k < 2; ++k) {
                    float keep = b1 ? val[k + 2] : val[k];
                    float send = b1 ? val[k]     : val[k + 2];
                    val[k] = keep + __shfl_xor_sync(0xffffffffu, send, 2);
                }
                {
                    float keep = b0 ? val[1] : val[0];
                    float send = b0 ? val[0] : val[1];
                    val[0] = keep + __shfl_xor_sync(0xffffffffu, send, 1);
                }
                val[0] += __shfl_xor_sync(0xffffffffu, val[0], 16);
                if (lane < 14) sh_GP[half][pb][lane][wh] = val[0];
            }
            __syncthreads();   // the ONLY barrier per block

            // phase 3: merge 2 warp partials, K-space recursion (exact)
            #define GSUM(e) ({ float2 qq = *(const float2*)&sh_GP[half][pb][e][0]; qq.x + qq.y; })
            float g00 = GSUM(0), u01 = GSUM(1), g11 = GSUM(2), u02 = GSUM(3);
            float g21 = GSUM(4), g22 = GSUM(5), u03 = GSUM(6), g31 = GSUM(7);
            float g32 = GSUM(8), g33 = GSUM(9);
            // z: each warp contributed exact z -> merged = 2*z
            float z0 = GSUM(10) * 0.5f, z1 = GSUM(11) * 0.5f;
            float z2 = GSUM(12) * 0.5f, z3 = GSUM(13) * 0.5f;
            #undef GSUM

            float rs0 = __fdividef(1.0f, g00 + sh_r[o + 0]);
            float c01 = u01 * rs0, c02 = u02 * rs0, c03 = u03 * rs0;
            float u12 = g21 - c01 * u02;
            float u13 = g31 - c01 * u03;
            float rs1 = __fdividef(1.0f, (g11 - c01 * u01) + sh_r[o + 1]);
            float c12 = u12 * rs1, c13 = u13 * rs1;
            float u23 = g32 - c02 * u03 - c12 * u13;
            float rs2 = __fdividef(1.0f, (g22 - c02 * u02 - c12 * u12) + sh_r[o + 2]);
            float c23 = u23 * rs2;
            float rs3 = __fdividef(1.0f, (g33 - c03 * u03 - c13 * u13 - c23 * u23) + sh_r[o + 3]);
            float f0 = (sh_y[half][o + 0] - z0) * rs0;
            float f1 = (sh_y[half][o + 1] - z1 - u01 * f0) * rs1;
            float f2 = (sh_y[half][o + 2] - z2 - u02 * f0 - u12 * f1) * rs2;
            float f3 = (sh_y[half][o + 3] - z3 - u03 * f0 - u13 * f1 - u23 * f2) * rs3;

            // phase 4: w col strips (packed), w row strips (scalar), rank-4, mu
            u64 wc[4][4];
            {
                const ulonglong2* q0 = (const ulonglong2*)&V[0 * 64 + c0];
                const ulonglong2* q1 = (const ulonglong2*)&V[1 * 64 + c0];
                const ulonglong2* q2 = (const ulonglong2*)&V[2 * 64 + c0];
                const ulonglong2* q3 = (const ulonglong2*)&V[3 * 64 + c0];
                ulonglong2 a0 = q0[0], e0 = q0[1];
                wc[0][0] = a0.x; wc[0][1] = a0.y; wc[0][2] = e0.x; wc[0][3] = e0.y;
                ulonglong2 a1 = q1[0], e1 = q1[1];
                wc[1][0] = a1.x; wc[1][1] = a1.y; wc[1][2] = e1.x; wc[1][3] = e1.y;
                ulonglong2 a2 = q2[0], e2 = q2[1];
                wc[2][0] = a2.x; wc[2][1] = a2.y; wc[2][2] = e2.x; wc[2][3] = e2.y;
                ulonglong2 a3 = q3[0], e3 = q3[1];
                wc[3][0] = a3.x; wc[3][1] = a3.y; wc[3][2] = e3.x; wc[3][3] = e3.y;
                u64 n01 = pk2(-c01, -c01), n02 = pk2(-c02, -c02), n03 = pk2(-c03, -c03);
                u64 n12 = pk2(-c12, -c12), n13 = pk2(-c13, -c13), n23 = pk2(-c23, -c23);
                #pragma unroll
                for (int k = 0; k < 4; ++k) {
                    ffma2(wc[1][k], n01, wc[0][k], wc[1][k]);
                    ffma2(wc[2][k], n02, wc[0][k], wc[2][k]);
                    ffma2(wc[2][k], n12, wc[1][k], wc[2][k]);
                    ffma2(wc[3][k], n03, wc[0][k], wc[3][k]);
                    ffma2(wc[3][k], n13, wc[1][k], wc[3][k]);
                    ffma2(wc[3][k], n23, wc[2][k], wc[3][k]);
                }
            }
            float wr[4][8];
            #pragma unroll
            for (int j = 0; j < 4; ++j) {
                float4 pa = *(const float4*)&V[(j << 6) + r0];
                float4 pe = *(const float4*)&V[(j << 6) + r0 + 4];
                wr[j][0] = pa.x; wr[j][1] = pa.y; wr[j][2] = pa.z; wr[j][3] = pa.w;
                wr[j][4] = pe.x; wr[j][5] = pe.y; wr[j][6] = pe.z; wr[j][7] = pe.w;
            }
            #pragma unroll
            for (int a = 0; a < 8; ++a) {
                wr[1][a] -= c01 * wr[0][a];
                wr[2][a] -= c02 * wr[0][a] + c12 * wr[1][a];
                wr[3][a] -= c03 * wr[0][a] + c13 * wr[1][a] + c23 * wr[2][a];
            }
            #pragma unroll
            for (int i = 0; i < 4; ++i) {
                float rsv = (i == 0) ? rs0 : (i == 1) ? rs1 : (i == 2) ? rs2 : rs3;
                #pragma unroll
                for (int a = 0; a < 8; ++a) {
                    float wsc = -wr[i][a] * rsv;
                    u64 g = pk2(wsc, wsc);
                    ffma2(P2[a][0], g, wc[i][0], P2[a][0]);
                    ffma2(P2[a][1], g, wc[i][1], P2[a][1]);
                    ffma2(P2[a][2], g, wc[i][2], P2[a][2]);
                    ffma2(P2[a][3], g, wc[i][3], P2[a][3]);
                }
            }
            {
                u64 f02 = pk2(f0, f0), f12 = pk2(f1, f1);
                u64 f22 = pk2(f2, f2), f32 = pk2(f3, f3);
                #pragma unroll
                for (int k = 0; k < 4; ++k) {
                    ffma2(mc2[k], f02, wc[0][k], mc2[k]);
                    ffma2(mc2[k], f12, wc[1][k], mc2[k]);
                    ffma2(mc2[k], f22, wc[2][k], mc2[k]);
                    ffma2(mc2[k], f32, wc[3][k], mc2[k]);
                }
            }
        }

        // ---- outputs ; publish mu for next predict ----
        if (ht < 8) {
            float2 m0f = up2(mc2[0]), m1f = up2(mc2[1]);
            float2 m2f = up2(mc2[2]), m3f = up2(mc2[3]);
            float4 lo = make_float4(m0f.x, m0f.y, m1f.x, m1f.y);
            float4 hi = make_float4(m2f.x, m2f.y, m3f.x, m3f.y);
            float* op = &outmu[((size_t)t * BATCH + b) * 64 + c0];
            *(float4*)op = lo;
            *(float4*)(op + 4) = hi;
            *(float4*)&sh_mu[half][c0] = lo;
            *(float4*)&sh_mu[half][c0 + 4] = hi;
        }
        if (diag) {
            #pragma unroll
            for (int a = 0; a < 8; ++a) {
                float2 e = up2(P2[a][a >> 1]);
                float dv = (a & 1) ? e.y : e.x;
                outls[((size_t)t * BATCH + b) * 64 + r0 + a] = 0.5f * logf(dv);
            }
        }
        __syncthreads();
    }
}

extern "C" void kernel_launch(void* const* d_in, const int* in_sizes, int n_in,
                              void* d_out, int out_size) {
    const float* ext  = (const float*)d_in[0];   // (500, 512, 32)
    const float* obs  = (const float*)d_in[1];   // (500, 512, 64)
    const float* mu0  = (const float*)d_in[2];   // (512, 64)
    const float* sg0  = (const float*)d_in[3];   // (512, 64)
    const float* lsig = (const float*)d_in[4];   // (64,)
    const float* Bm   = (const float*)d_in[5];   // (64, 32)
    const float* H    = (const float*)d_in[6];   // (64, 64)
    const float* ldel = (const float*)d_in[7];   // (64,)
    float* out = (float*)d_out;

    akf_main<<<BATCH / 2, 128>>>(ext, obs, mu0, sg0, lsig, Bm, H, ldel, out);
}

// round 12
// speedup vs baseline: 1.2048x; 1.0299x over previous
#include <cuda_runtime.h>
#include <math.h>

#define TSEQ 500
#define BATCH 512

typedef unsigned long long u64;

__device__ __forceinline__ void ffma2(u64& d, u64 a, u64 b, u64 c) {
    asm("fma.rn.f32x2 %0, %1, %2, %3;" : "=l"(d) : "l"(a), "l"(b), "l"(c));
}
__device__ __forceinline__ u64 fmul2(u64 a, u64 b) {
    u64 d; asm("mul.rn.f32x2 %0, %1, %2;" : "=l"(d) : "l"(a), "l"(b)); return d;
}
__device__ __forceinline__ float2 up2(u64 v) {
    float2 f; asm("mov.b64 {%0,%1}, %2;" : "=f"(f.x), "=f"(f.y) : "l"(v)); return f;
}
__device__ __forceinline__ u64 pk2(float x, float y) {
    u64 v; asm("mov.b64 %0, {%1,%2};" : "=l"(v) : "f"(x), "f"(y)); return v;
}
// 64-thread named barrier scoped to one batch-half (ids 1 and 2)
__device__ __forceinline__ void barh(int half) {
    asm volatile("bar.sync %0, 64;" :: "r"(half + 1) : "memory");
}

// CTA = 128 threads = 2 INDEPENDENT batch-halves of 64 threads (2 warps each),
// decoupled by named barriers so their phases slip freely (4 streams/SM).
// Within a half: ht = tid&63, rg = ht>>3 (8 row-groups x 8 rows), cg = ht&7.
// Thread owns P[8rg..8rg+7][8cg..8cg+7] as P2[8][4] packed f32x2.
// K=4 blocked sequential measurement updates, ONE (named) barrier per block.

__global__ void __launch_bounds__(128, 2)
akf_main(const float* __restrict__ ext, const float* __restrict__ obs,
         const float* __restrict__ mu0, const float* __restrict__ sg0,
         const float* __restrict__ lsig, const float* __restrict__ Bm,
         const float* __restrict__ Hm, const float* __restrict__ ldel,
         float* __restrict__ out)
{
    __shared__ __align__(16) float sh_H[4096];
    __shared__ __align__(16) float sh_B[2048];
    __shared__ __align__(16) float sh_V[2][2][4][64];   // [half][pb][j][row]
    __shared__ __align__(16) float sh_GP[2][2][14][2];  // [half][pb][entry][warp]
    __shared__ __align__(16) float sh_mu[2][64];
    __shared__ __align__(16) float sh_y[2][64];
    __shared__ float sh_u[2][32], sh_r[64], sh_q[64];

    const int tid  = threadIdx.x;
    const int half = tid >> 6;
    const int ht   = tid & 63;
    const int b    = (blockIdx.x << 1) | half;
    const int rg   = ht >> 3;
    const int cg   = ht & 7;
    const int r0   = rg << 3;
    const int c0   = cg << 3;
    const int lane = tid & 31;
    const int wh   = (ht >> 5) & 1;
    const bool zon = (lane < 8);
    const bool diag = (rg == cg);
    const bool bb2 = cg & 4, bb1 = cg & 2, bb0 = cg & 1;

    for (int i = tid; i < 4096; i += 128) sh_H[i] = Hm[i];
    for (int i = tid; i < 2048; i += 128) sh_B[i] = Bm[i];
    if (tid < 64) {
        float e = expf(ldel[tid]); sh_r[tid] = e * e;
        float f = expf(lsig[tid]); sh_q[tid] = f * f;
    }

    u64 P2[8][4];
    #pragma unroll
    for (int a = 0; a < 8; ++a)
        #pragma unroll
        for (int k = 0; k < 4; ++k) P2[a][k] = 0ull;

    float* outmu = out;
    float* outls = out + (size_t)TSEQ * BATCH * 64;

    {
        float m0  = mu0[b * 64 + ht];
        float s0v = sg0[b * 64 + ht];
        sh_mu[half][ht] = m0;
        outmu[b * 64 + ht] = m0;
        outls[b * 64 + ht] = logf(s0v);
    }
    if (diag) {
        #pragma unroll
        for (int a = 0; a < 8; ++a) {
            float s0v = sg0[b * 64 + r0 + a];
            float2 e = up2(P2[a][a >> 1]);
            if (a & 1) e.y = s0v * s0v; else e.x = s0v * s0v;
            P2[a][a >> 1] = pk2(e.x, e.y);
        }
    }
    __syncthreads();   // full-CTA: sh_H/sh_B/sh_r/sh_q visible to both halves

    for (int t = 1; t < TSEQ; ++t) {
        sh_y[half][ht] = obs[((size_t)t * BATCH + b) * 64 + ht];
        if (ht < 32) sh_u[half][ht] = ext[((size_t)(t - 1) * BATCH + b) * 32 + ht];
        barh(half);

        // ---- predict: mu += B u ; P += diag(q) ----
        {
            float s = sh_mu[half][ht];
            const float* Br = &sh_B[ht * 32];
            #pragma unroll 8
            for (int k = 0; k < 32; ++k) s += Br[k] * sh_u[half][k];
            sh_mu[half][ht] = s;
        }
        if (diag) {
            #pragma unroll
            for (int a = 0; a < 8; ++a) {
                float qv = sh_q[r0 + a];
                float2 e = up2(P2[a][a >> 1]);
                if (a & 1) e.y += qv; else e.x += qv;
                P2[a][a >> 1] = pk2(e.x, e.y);
            }
        }
        barh(half);

        // mu col strip -> every thread's registers (replicated)
        u64 mc2[4];
        {
            const ulonglong2* mp = (const ulonglong2*)&sh_mu[half][c0];
            ulonglong2 ma = mp[0], mb = mp[1];
            mc2[0] = ma.x; mc2[1] = ma.y; mc2[2] = mb.x; mc2[3] = mb.y;
        }

        // ---- 16 blocks of 4 observations, one named barrier each ----
        #pragma unroll 1
        for (int blk = 0; blk < 16; ++blk) {
            const int o  = blk << 2;
            const int pb = blk & 1;
            float* V = &sh_V[half][pb][0][0];

            // phase 1a: vp[j][a] partials, V rows, z partials
            float vp[4][8];
            float zz[4];
            #pragma unroll
            for (int j = 0; j < 4; ++j) {
                const ulonglong2* hp = (const ulonglong2*)&sh_H[((o + j) << 6) + c0];
                ulonglong2 ha = hp[0], hb = hp[1];
                u64 h2[4] = {ha.x, ha.y, hb.x, hb.y};
                #pragma unroll
                for (int a = 0; a < 8; ++a) {
                    u64 acc = 0ull;
                    ffma2(acc, P2[a][0], h2[0], acc);
                    ffma2(acc, P2[a][1], h2[1], acc);
                    ffma2(acc, P2[a][2], h2[2], acc);
                    ffma2(acc, P2[a][3], h2[3], acc);
                    float2 f = up2(acc);
                    vp[j][a] = f.x + f.y;
                }
                // reduce-scatter 8 values over the 8-lane octet (7 shuffles)
                float k4[4], k2[2];
                #pragma unroll
                for (int m = 0; m < 4; ++m) {
                    float keep = bb2 ? vp[j][m + 4] : vp[j][m];
                    float send = bb2 ? vp[j][m]     : vp[j][m + 4];
                    k4[m] = keep + __shfl_xor_sync(0xffffffffu, send, 4);
                }
                #pragma unroll
                for (int m = 0; m < 2; ++m) {
                    float keep = bb1 ? k4[m + 2] : k4[m];
                    float send = bb1 ? k4[m]     : k4[m + 2];
                    k2[m] = keep + __shfl_xor_sync(0xffffffffu, send, 2);
                }
                float keep = bb0 ? k2[1] : k2[0];
                float send = bb0 ? k2[0] : k2[1];
                float kk = keep + __shfl_xor_sync(0xffffffffu, send, 1);
                V[(j << 6) + ht] = kk;
                // innovation partial (counted once per warp via zon)
                u64 za = 0ull;
                ffma2(za, h2[0], mc2[0], za);
                ffma2(za, h2[1], mc2[1], za);
                ffma2(za, h2[2], mc2[2], za);
                ffma2(za, h2[3], mc2[3], za);
                float2 zf = up2(za);
                zz[j] = zon ? (zf.x + zf.y) : 0.0f;
            }

            // phase 1b: Gram partials + 16-value/16-lane butterfly reduce-scatter
            {
                float4 hqa[4], hqb[4];
                #pragma unroll
                for (int j = 0; j < 4; ++j) {
                    hqa[j] = *(const float4*)&sh_H[((o + j) << 6) + r0];
                    hqb[j] = *(const float4*)&sh_H[((o + j) << 6) + r0 + 4];
                }
                #define DOT8(j, k) (hqa[j].x*vp[k][0] + hqa[j].y*vp[k][1] + hqa[j].z*vp[k][2] + hqa[j].w*vp[k][3] \
                                  + hqb[j].x*vp[k][4] + hqb[j].y*vp[k][5] + hqb[j].z*vp[k][6] + hqb[j].w*vp[k][7])
                float val[16];
                val[0] = DOT8(0, 0); val[1] = DOT8(1, 0); val[2] = DOT8(1, 1);
                val[3] = DOT8(2, 0); val[4] = DOT8(2, 1); val[5] = DOT8(2, 2);
                val[6] = DOT8(3, 0); val[7] = DOT8(3, 1); val[8] = DOT8(3, 2);
                val[9] = DOT8(3, 3);
                #undef DOT8
                val[10] = zz[0]; val[11] = zz[1]; val[12] = zz[2]; val[13] = zz[3];
                val[14] = 0.0f;  val[15] = 0.0f;

                const bool b3 = lane & 8, b2l = lane & 4, b1 = lane & 2, b0 = lane & 1;
                #pragma unroll
                for (int k = 0; k < 8; ++k) {
                    float keep = b3 ? val[k + 8] : val[k];
                    float send = b3 ? val[k]     : val[k + 8];
                    val[k] = keep + __shfl_xor_sync(0xffffffffu, send, 8);
                }
                #pragma unroll
                for (int k = 0; k < 4; ++k) {
                    float keep = b2l ? val[k + 4] : val[k];
                    float send = b2l ? val[k]     : val[k + 4];
                    val[k] = keep + __shfl_xor_sync(0xffffffffu, send, 4);
                }
                #pragma unroll
                for (int k = 0; k < 2; ++k) {
                    float keep = b1 ? val[k + 2] : val[k];
                    float send = b1 ? val[k]     : val[k + 2];
                    val[k] = keep + __shfl_xor_sync(0xffffffffu, send, 2);
                }
                {
                    float keep = b0 ? val[1] : val[0];
                    float send = b0 ? val[0] : val[1];
                    val[0] = keep + __shfl_xor_sync(0xffffffffu, send, 1);
                }
                val[0] += __shfl_xor_sync(0xffffffffu, val[0], 16);
                if (lane < 14) sh_GP[half][pb][lane][wh] = val[0];
            }
            barh(half);   // the ONLY barrier per block (half-scoped)

            // phase 3: merge 2 warp partials, K-space recursion (exact)
            #define GSUM(e) ({ float2 qq = *(const float2*)&sh_GP[half][pb][e][0]; qq.x + qq.y; })
            float g00 = GSUM(0), u01 = GSUM(1), g11 = GSUM(2), u02 = GSUM(3);
            float g21 = GSUM(4), g22 = GSUM(5), u03 = GSUM(6), g31 = GSUM(7);
            float g32 = GSUM(8), g33 = GSUM(9);
            float z0 = GSUM(10) * 0.5f, z1 = GSUM(11) * 0.5f;
            float z2 = GSUM(12) * 0.5f, z3 = GSUM(13) * 0.5f;
            #undef GSUM

            float rs0 = __fdividef(1.0f, g00 + sh_r[o + 0]);
            float c01 = u01 * rs0, c02 = u02 * rs0, c03 = u03 * rs0;
            float u12 = g21 - c01 * u02;
            float u13 = g31 - c01 * u03;
            float rs1 = __fdividef(1.0f, (g11 - c01 * u01) + sh_r[o + 1]);
            float c12 = u12 * rs1, c13 = u13 * rs1;
            float u23 = g32 - c02 * u03 - c12 * u13;
            float rs2 = __fdividef(1.0f, (g22 - c02 * u02 - c12 * u12) + sh_r[o + 2]);
            float c23 = u23 * rs2;
            float rs3 = __fdividef(1.0f, (g33 - c03 * u03 - c13 * u13 - c23 * u23) + sh_r[o + 3]);
            float f0 = (sh_y[half][o + 0] - z0) * rs0;
            float f1 = (sh_y[half][o + 1] - z1 - u01 * f0) * rs1;
            float f2 = (sh_y[half][o + 2] - z2 - u02 * f0 - u12 * f1) * rs2;
            float f3 = (sh_y[half][o + 3] - z3 - u03 * f0 - u13 * f1 - u23 * f2) * rs3;

            // phase 4: w col strips (packed), mu update (unscaled), pre-scaled rank-4
            u64 wc[4][4];
            {
                const ulonglong2* q0 = (const ulonglong2*)&V[0 * 64 + c0];
                const ulonglong2* q1 = (const ulonglong2*)&V[1 * 64 + c0];
                const ulonglong2* q2 = (const ulonglong2*)&V[2 * 64 + c0];
                const ulonglong2* q3 = (const ulonglong2*)&V[3 * 64 + c0];
                ulonglong2 a0 = q0[0], e0 = q0[1];
                wc[0][0] = a0.x; wc[0][1] = a0.y; wc[0][2] = e0.x; wc[0][3] = e0.y;
                ulonglong2 a1 = q1[0], e1 = q1[1];
                wc[1][0] = a1.x; wc[1][1] = a1.y; wc[1][2] = e1.x; wc[1][3] = e1.y;
                ulonglong2 a2 = q2[0], e2 = q2[1];
                wc[2][0] = a2.x; wc[2][1] = a2.y; wc[2][2] = e2.x; wc[2][3] = e2.y;
                ulonglong2 a3 = q3[0], e3 = q3[1];
                wc[3][0] = a3.x; wc[3][1] = a3.y; wc[3][2] = e3.x; wc[3][3] = e3.y;
                u64 n01 = pk2(-c01, -c01), n02 = pk2(-c02, -c02), n03 = pk2(-c03, -c03);
                u64 n12 = pk2(-c12, -c12), n13 = pk2(-c13, -c13), n23 = pk2(-c23, -c23);
                #pragma unroll
                for (int k = 0; k < 4; ++k) {
                    ffma2(wc[1][k], n01, wc[0][k], wc[1][k]);
                    ffma2(wc[2][k], n02, wc[0][k], wc[2][k]);
                    ffma2(wc[2][k], n12, wc[1][k], wc[2][k]);
                    ffma2(wc[3][k], n03, wc[0][k], wc[3][k]);
                    ffma2(wc[3][k], n13, wc[1][k], wc[3][k]);
                    ffma2(wc[3][k], n23, wc[2][k], wc[3][k]);
                }
            }
            // mu += sum_i f_i * w_i  (uses UNSCALED wc; bitwise identical to R11)
            {
                u64 f02 = pk2(f0, f0), f12 = pk2(f1, f1);
                u64 f22 = pk2(f2, f2), f32 = pk2(f3, f3);
                #pragma unroll
                for (int k = 0; k < 4; ++k) {
                    ffma2(mc2[k], f02, wc[0][k], mc2[k]);
                    ffma2(mc2[k], f12, wc[1][k], mc2[k]);
                    ffma2(mc2[k], f22, wc[2][k], mc2[k]);
                    ffma2(mc2[k], f32, wc[3][k], mc2[k]);
                }
            }
            // pre-scale wc by -rs_i, then rank-4 with pk2(wr) multipliers
            {
                u64 m0s = pk2(-rs0, -rs0), m1s = pk2(-rs1, -rs1);
                u64 m2s = pk2(-rs2, -rs2), m3s = pk2(-rs3, -rs3);
                #pragma unroll
                for (int k = 0; k < 4; ++k) {
                    wc[0][k] = fmul2(wc[0][k], m0s);
                    wc[1][k] = fmul2(wc[1][k], m1s);
                    wc[2][k] = fmul2(wc[2][k], m2s);
                    wc[3][k] = fmul2(wc[3][k], m3s);
                }
            }
            float wr[4][8];
            #pragma unroll
            for (int j = 0; j < 4; ++j) {
                float4 pa = *(const float4*)&V[(j << 6) + r0];
                float4 pe = *(const float4*)&V[(j << 6) + r0 + 4];
                wr[j][0] = pa.x; wr[j][1] = pa.y; wr[j][2] = pa.z; wr[j][3] = pa.w;
                wr[j][4] = pe.x; wr[j][5] = pe.y; wr[j][6] = pe.z; wr[j][7] = pe.w;
            }
            #pragma unroll
            for (int a = 0; a < 8; ++a) {
                wr[1][a] -= c01 * wr[0][a];
                wr[2][a] -= c02 * wr[0][a] + c12 * wr[1][a];
                wr[3][a] -= c03 * wr[0][a] + c13 * wr[1][a] + c23 * wr[2][a];
            }
            #pragma unroll
            for (int i = 0; i < 4; ++i) {
                #pragma unroll
                for (int a = 0; a < 8; ++a) {
                    u64 g = pk2(wr[i][a], wr[i][a]);
                    ffma2(P2[a][0], g, wc[i][0], P2[a][0]);
                    ffma2(P2[a][1], g, wc[i][1], P2[a][1]);
                    ffma2(P2[a][2], g, wc[i][2], P2[a][2]);
                    ffma2(P2[a][3], g, wc[i][3], P2[a][3]);
                }
            }
        }

        // ---- outputs ; publish mu for next predict ----
        if (ht < 8) {
            float2 m0f = up2(mc2[0]), m1f = up2(mc2[1]);
            float2 m2f = up2(mc2[2]), m3f = up2(mc2[3]);
            float4 lo = make_float4(m0f.x, m0f.y, m1f.x, m1f.y);
            float4 hi = make_float4(m2f.x, m2f.y, m3f.x, m3f.y);
            float* op = &outmu[((size_t)t * BATCH + b) * 64 + c0];
            *(float4*)op = lo;
            *(float4*)(op + 4) = hi;
            *(float4*)&sh_mu[half][c0] = lo;
            *(float4*)&sh_mu[half][c0 + 4] = hi;
        }
        if (diag) {
            #pragma unroll
            for (int a = 0; a < 8; ++a) {
                float2 e = up2(P2[a][a >> 1]);
                float dv = (a & 1) ? e.y : e.x;
                outls[((size_t)t * BATCH + b) * 64 + r0 + a] = 0.5f * logf(dv);
            }
        }
        barh(half);
    }
}

extern "C" void kernel_launch(void* const* d_in, const int* in_sizes, int n_in,
                              void* d_out, int out_size) {
    const float* ext  = (const float*)d_in[0];   // (500, 512, 32)
    const float* obs  = (const float*)d_in[1];   // (500, 512, 64)
    const float* mu0  = (const float*)d_in[2];   // (512, 64)
    const float* sg0  = (const float*)d_in[3];   // (512, 64)
    const float* lsig = (const float*)d_in[4];   // (64,)
    const float* Bm   = (const float*)d_in[5];   // (64, 32)
    const float* H    = (const float*)d_in[6];   // (64, 64)
    const float* ldel = (const float*)d_in[7];   // (64,)
    float* out = (float*)d_out;

    akf_main<<<BATCH / 2, 128>>>(ext, obs, mu0, sg0, lsig, Bm, H, ldel, out);
}